// round 7
// baseline (speedup 1.0000x reference)
#include <cuda_runtime.h>
#include <cstdint>

// Problem constants (from reference)
constexpr int B_ = 32;
constexpr int Q_ = 16384;
constexpr int G_ = 128;
constexpr int N_ = 9;

#define FULLM 0xFFFFFFFFu

__device__ __forceinline__ uint64_t warp_max64(uint64_t v) {
#pragma unroll
    for (int o = 16; o; o >>= 1) {
        uint64_t u = __shfl_xor_sync(FULLM, v, o);
        v = (u > v) ? u : v;
    }
    return v;
}

__global__ void __launch_bounds__(128)
atss_kernel(const float4* __restrict__ pred,
            const float4* __restrict__ gt,
            float* __restrict__ out,          // <-- float32 output hypothesis
            int out_elems) {
    const int wid  = (blockIdx.x * blockDim.x + threadIdx.x) >> 5;  // 0..4095
    const int lane = threadIdx.x & 31;
    const int b = wid >> 7;        // / G_  (G_ = 128)
    const int g = wid & (G_ - 1);

    const float4* __restrict__ pb = pred + (size_t)b * Q_;
    const float4 gv = gt[b * G_ + g];

    // ---- Stage 1: top-32 smallest (d2, idx). Key = (d2_bits << 32) | idx. ----
    // d2 >= 0 so float bits compare like uint. One pool entry per lane.
    uint64_t pool     = ~0ull;
    uint64_t curmax   = ~0ull;        // warp-uniform max of pool
    unsigned cm2_bits = 0xFFFFFFFFu;  // high word of curmax (prefilter)

#pragma unroll 4
    for (int t = 0; t < Q_ / 32; t++) {
        const int i = (t << 5) + lane;
        const float4 p = __ldg(pb + i);
        // d2 with explicit rn ops, no FMA contraction; sequential add order
        // matches XLA's reduce emitter.
        const float dx = __fsub_rn(gv.x, p.x);
        const float dy = __fsub_rn(gv.y, p.y);
        const float dw = __fsub_rn(gv.z, p.z);
        const float dh = __fsub_rn(gv.w, p.w);
        const float d2 = __fadd_rn(__fadd_rn(__fadd_rn(
                             __fmul_rn(dx, dx), __fmul_rn(dy, dy)),
                             __fmul_rn(dw, dw)), __fmul_rn(dh, dh));
        const unsigned d2b = __float_as_uint(d2);

        // Prefilter: only keys with d2b <= cm2_bits can beat curmax.
        unsigned m = __ballot_sync(FULLM, d2b <= cm2_bits);
        while (m) {
            const int src = __ffs(m) - 1;
            m &= m - 1;
            const unsigned cb = __shfl_sync(FULLM, d2b, src);
            const unsigned ci = (unsigned)__shfl_sync(FULLM, i, src);
            const uint64_t cand = ((uint64_t)cb << 32) | ci;
            if (cand < curmax) {                 // warp-uniform exact test
                const unsigned bm = __ballot_sync(FULLM, pool == curmax);
                if (lane == __ffs(bm) - 1) pool = cand;
                curmax = warp_max64(pool);
                cm2_bits = (unsigned)(curmax >> 32);
            }
        }
    }

    // ---- Re-rank by (sqrt(d2) bits, idx) == JAX's (d, idx) order, then sort --
    const unsigned pidx_raw = (unsigned)(pool & 0xFFFFFFFFull);
    const float dval = __fsqrt_rn(__uint_as_float((unsigned)(pool >> 32)));
    uint64_t skey = ((uint64_t)__float_as_uint(dval) << 32) | pidx_raw;

    // Bitonic sort ascending across the warp; rank = lane after sort
#pragma unroll
    for (int k = 2; k <= 32; k <<= 1) {
#pragma unroll
        for (int j = k >> 1; j; j >>= 1) {
            const uint64_t other = __shfl_xor_sync(FULLM, skey, j);
            const bool lower = (lane & j) == 0;
            const bool asc   = (lane & k) == 0;
            const uint64_t mn = (skey < other) ? skey : other;
            const uint64_t mx = (skey < other) ? other : skey;
            skey = (lower == asc) ? mn : mx;
        }
    }
    const unsigned pidx = (unsigned)(skey & 0xFFFFFFFFull);
    const int rank = lane;                      // 0 = nearest (JAX kidx order)

    // ---- Stage 2: IoU(gt, candidate), explicit rn ops (no contraction) ------
    const float4 p = __ldg(pb + pidx);
    const float gx0 = __fsub_rn(gv.x, __fmul_rn(0.5f, gv.z));
    const float gx1 = __fadd_rn(gv.x, __fmul_rn(0.5f, gv.z));
    const float gy0 = __fsub_rn(gv.y, __fmul_rn(0.5f, gv.w));
    const float gy1 = __fadd_rn(gv.y, __fmul_rn(0.5f, gv.w));
    const float px0 = __fsub_rn(p.x,  __fmul_rn(0.5f, p.z));
    const float px1 = __fadd_rn(p.x,  __fmul_rn(0.5f, p.z));
    const float py0 = __fsub_rn(p.y,  __fmul_rn(0.5f, p.w));
    const float py1 = __fadd_rn(p.y,  __fmul_rn(0.5f, p.w));

    const float ltx = fmaxf(gx0, px0), lty = fmaxf(gy0, py0);
    const float rbx = fminf(gx1, px1), rby = fminf(gy1, py1);
    const float iw = fmaxf(__fsub_rn(rbx, ltx), 0.0f);
    const float ih = fmaxf(__fsub_rn(rby, lty), 0.0f);
    const float inter = __fmul_rn(iw, ih);
    const float areaA = __fmul_rn(__fsub_rn(gx1, gx0), __fsub_rn(gy1, gy0));
    const float areaB = __fmul_rn(__fsub_rn(px1, px0), __fsub_rn(py1, py0));
    const float uni   = __fsub_rn(__fadd_rn(areaA, areaB), inter);
    const float iou   = __fdiv_rn(inter, uni);

    // ---- top-9 by IoU, ties -> smaller rank (stable, matches lax.top_k) -----
    // key = (iou_bits << 32) | (32 - rank); keys unique, live keys >= 1 > 0.
    uint64_t ikey = ((uint64_t)__float_as_uint(iou) << 32) | (unsigned)(32 - rank);

    const int obase = wid * N_;
#pragma unroll
    for (int n = 0; n < N_; n++) {
        const uint64_t m = warp_max64(ikey);
        if (ikey == m) {                 // exactly one lane (keys unique)
            if (obase + n < out_elems) out[obase + n] = (float)pidx;  // numeric value
            ikey = 0;
        }
    }
    // gt_idx half (only if buffer holds both outputs)
    const int gbase = B_ * G_ * N_ + obase;
    if (lane < N_ && gbase + lane < out_elems) out[gbase + lane] = (float)g;
}

extern "C" void kernel_launch(void* const* d_in, const int* in_sizes, int n_in,
                              void* d_out, int out_size) {
    // pred_boxes [B,Q,4] is the strictly larger input in any size unit;
    // identify by relative size (robust to metadata being sorted by name).
    const float4* pred = (const float4*)d_in[0];
    const float4* gt   = (const float4*)d_in[1];
    if (n_in >= 2 && in_sizes[0] < in_sizes[1]) {
        pred = (const float4*)d_in[1];
        gt   = (const float4*)d_in[0];
    }
    const int total_warps = B_ * G_;                 // 4096
    const int threads = 128;                         // 4 warps/CTA
    const int blocks = total_warps / (threads / 32); // 1024
    atss_kernel<<<blocks, threads>>>(pred, gt, (float*)d_out, out_size);
}

// round 8
// speedup vs baseline: 1.3051x; 1.3051x over previous
#include <cuda_runtime.h>
#include <cstdint>

constexpr int B_ = 32;
constexpr int Q_ = 16384;
constexpr int G_ = 128;
constexpr int N_ = 9;
constexpr int HALF_Q = Q_ / 2;         // 8192 per warp
constexpr int GROUPS = HALF_Q / 128;   // 64 groups of 4x32 candidates

#define FULLM 0xFFFFFFFFu

// Sentinel key: hi = +inf bits (so float threshold = +inf accepts everything),
// greater than any real key (real d2 <= 4.0 << inf).
#define SENT (((uint64_t)0x7F800000u << 32) | 0xFFFFFFFFull)

__global__ void __launch_bounds__(128)
atss_kernel(const float4* __restrict__ pred,
            const float4* __restrict__ gt,
            float* __restrict__ out,
            int out_elems) {
    const int wic  = threadIdx.x >> 5;   // warp in CTA: 0..3
    const int lane = threadIdx.x & 31;
    const int pair = wic >> 1;           // GT slot within CTA: 0..1
    const int half = wic & 1;            // which half of Q this warp scans
    const int gt_lin = blockIdx.x * 2 + pair;        // 0..4095
    const int b = gt_lin >> 7;                       // / G_
    const int g = gt_lin & (G_ - 1);

    const float4* __restrict__ pb = pred + (size_t)b * Q_;
    const float4 gv = gt[gt_lin];
    const float4* __restrict__ ph = pb + half * HALF_Q;
    const int ibase0 = half * HALF_Q;

    // ---- Stage 1: this warp's top-32 smallest (d2, idx) over its Q half. ----
    // pool: sorted ascending across lanes, key = (d2_bits << 32) | idx.
    uint64_t pool   = SENT;
    uint64_t curmax = SENT;                       // == pool[31], warp-uniform
    float    t2f    = __uint_as_float(0x7F800000u);  // +inf threshold

    for (int t = 0; t < GROUPS; t++) {
        const float4* gp = ph + t * 128 + lane;
        const float4 p0 = __ldg(gp);
        const float4 p1 = __ldg(gp + 32);
        const float4 p2 = __ldg(gp + 64);
        const float4 p3 = __ldg(gp + 96);

        float d2a[4];
        {   // exact rn chain (XLA-matching), 4 independent chains for ILP
            #define D2(dst, P) { \
                const float dx = __fsub_rn(gv.x, (P).x); \
                const float dy = __fsub_rn(gv.y, (P).y); \
                const float dw = __fsub_rn(gv.z, (P).z); \
                const float dh = __fsub_rn(gv.w, (P).w); \
                dst = __fadd_rn(__fadd_rn(__fadd_rn( \
                          __fmul_rn(dx, dx), __fmul_rn(dy, dy)), \
                          __fmul_rn(dw, dw)), __fmul_rn(dh, dh)); }
            D2(d2a[0], p0) D2(d2a[1], p1) D2(d2a[2], p2) D2(d2a[3], p3)
            #undef D2
        }

        const float mn = fminf(fminf(d2a[0], d2a[1]), fminf(d2a[2], d2a[3]));
        if (__any_sync(FULLM, mn <= t2f)) {
            const int base = ibase0 + t * 128;
            #pragma unroll
            for (int j = 0; j < 4; j++) {
                unsigned m = __ballot_sync(FULLM, d2a[j] <= t2f);
                while (m) {
                    const int src = __ffs(m) - 1;
                    m &= m - 1;
                    const float cf = __shfl_sync(FULLM, d2a[j], src);
                    const unsigned ci = (unsigned)(base + j * 32 + src);
                    const uint64_t cand =
                        ((uint64_t)__float_as_uint(cf) << 32) | ci;
                    if (cand < curmax) {          // warp-uniform exact test
                        // sorted-shift insertion: lanes holding keys > cand
                        // shift up by one; boundary lane takes cand.
                        const unsigned gtm = __ballot_sync(FULLM, pool > cand);
                        const uint64_t prev = __shfl_up_sync(FULLM, pool, 1);
                        const int ppos = __ffs(gtm) - 1;
                        if (pool > cand) pool = (lane == ppos) ? cand : prev;
                        curmax = __shfl_sync(FULLM, pool, 31);
                        t2f = __uint_as_float((unsigned)(curmax >> 32));
                    }
                }
            }
        }
    }

    // ---- Merge the two half-pools (exact): lower half of bitonic merge. ----
    __shared__ uint64_t sp[2][32];
    if (half == 1) sp[pair][lane] = pool;
    __syncthreads();
    if (half == 1) return;                        // warp 1 done

    {
        const uint64_t bk = sp[pair][31 - lane];  // other pool, reversed
        uint64_t v = (pool < bk) ? pool : bk;     // 32 smallest; bitonic seq
        #pragma unroll
        for (int j = 16; j; j >>= 1) {            // clean -> sorted ascending
            const uint64_t o = __shfl_xor_sync(FULLM, v, j);
            const uint64_t mnv = (v < o) ? v : o;
            const uint64_t mxv = (v < o) ? o : v;
            v = ((lane & j) == 0) ? mnv : mxv;
        }
        pool = v;
    }

    // ---- Re-rank by (sqrt(d2) bits, idx) == JAX's (d, idx); full sort. ------
    unsigned pidx = (unsigned)(pool & 0xFFFFFFFFull);
    {
        const float dval = __fsqrt_rn(__uint_as_float((unsigned)(pool >> 32)));
        uint64_t skey = ((uint64_t)__float_as_uint(dval) << 32) | pidx;
        #pragma unroll
        for (int k = 2; k <= 32; k <<= 1) {
            #pragma unroll
            for (int j = k >> 1; j; j >>= 1) {
                const uint64_t o = __shfl_xor_sync(FULLM, skey, j);
                const bool lower = (lane & j) == 0;
                const bool asc   = (lane & k) == 0;
                const uint64_t mnv = (skey < o) ? skey : o;
                const uint64_t mxv = (skey < o) ? o : skey;
                skey = (lower == asc) ? mnv : mxv;
            }
        }
        pidx = (unsigned)(skey & 0xFFFFFFFFull);
    }
    const int rank = lane;                        // 0 = nearest

    // ---- Stage 2: IoU(gt, candidate), explicit rn ops (no contraction). -----
    const float4 p = __ldg(pb + pidx);
    const float gx0 = __fsub_rn(gv.x, __fmul_rn(0.5f, gv.z));
    const float gx1 = __fadd_rn(gv.x, __fmul_rn(0.5f, gv.z));
    const float gy0 = __fsub_rn(gv.y, __fmul_rn(0.5f, gv.w));
    const float gy1 = __fadd_rn(gv.y, __fmul_rn(0.5f, gv.w));
    const float px0 = __fsub_rn(p.x,  __fmul_rn(0.5f, p.z));
    const float px1 = __fadd_rn(p.x,  __fmul_rn(0.5f, p.z));
    const float py0 = __fsub_rn(p.y,  __fmul_rn(0.5f, p.w));
    const float py1 = __fadd_rn(p.y,  __fmul_rn(0.5f, p.w));

    const float ltx = fmaxf(gx0, px0), lty = fmaxf(gy0, py0);
    const float rbx = fminf(gx1, px1), rby = fminf(gy1, py1);
    const float iw = fmaxf(__fsub_rn(rbx, ltx), 0.0f);
    const float ih = fmaxf(__fsub_rn(rby, lty), 0.0f);
    const float inter = __fmul_rn(iw, ih);
    const float areaA = __fmul_rn(__fsub_rn(gx1, gx0), __fsub_rn(gy1, gy0));
    const float areaB = __fmul_rn(__fsub_rn(px1, px0), __fsub_rn(py1, py0));
    const float uni   = __fsub_rn(__fadd_rn(areaA, areaB), inter);
    const float iou   = __fdiv_rn(inter, uni);

    // ---- top-9 by IoU, ties -> smaller rank: descending bitonic sort. -------
    // key = (iou_bits << 32) | (32 - rank): unique; low 6 bits recover rank.
    uint64_t ikey = ((uint64_t)__float_as_uint(iou) << 32)
                  | (unsigned)(32 - rank);
    #pragma unroll
    for (int k = 2; k <= 32; k <<= 1) {
        #pragma unroll
        for (int j = k >> 1; j; j >>= 1) {
            const uint64_t o = __shfl_xor_sync(FULLM, ikey, j);
            const bool lower = (lane & j) == 0;
            const bool desc  = (lane & k) == 0;
            const uint64_t mnv = (ikey < o) ? ikey : o;
            const uint64_t mxv = (ikey < o) ? o : ikey;
            ikey = (lower == desc) ? mxv : mnv;   // descending
        }
    }
    const int rsel = 32 - (int)(ikey & 63);       // original rank of this entry
    const unsigned psel = __shfl_sync(FULLM, pidx, rsel);

    const int obase = gt_lin * N_;
    if (lane < N_ && obase + lane < out_elems)
        out[obase + lane] = (float)psel;
    const int gbase = B_ * G_ * N_ + obase;
    if (lane < N_ && gbase + lane < out_elems)
        out[gbase + lane] = (float)g;
}

extern "C" void kernel_launch(void* const* d_in, const int* in_sizes, int n_in,
                              void* d_out, int out_size) {
    const float4* pred = (const float4*)d_in[0];
    const float4* gt   = (const float4*)d_in[1];
    if (n_in >= 2 && in_sizes[0] < in_sizes[1]) {   // robust input ordering
        pred = (const float4*)d_in[1];
        gt   = (const float4*)d_in[0];
    }
    // 2 GTs per CTA (4 warps: 2 warps per GT), 4096 GTs -> 2048 CTAs
    atss_kernel<<<(B_ * G_) / 2, 128>>>(pred, gt, (float*)d_out, out_size);
}